// round 12
// baseline (speedup 1.0000x reference)
#include <cuda_runtime.h>
#include <cstdint>

#define MAX_SEG 100001
#define SPB 8            // segments per block (4 warps x 2 segments/warp)
#define SMEM_IDX 2048    // indices staged per block (8 segments, mean ~102 edges)

// scratch (no cudaMalloc allowed)
__device__ int g_offsets[MAX_SEG + 1];

// ---------------------------------------------------------------------------
// Packed-f32 helpers (sm_103a f32x2 pipe) + raw 128-bit global load.
// ---------------------------------------------------------------------------
struct U2 { unsigned long long lo, hi; };

__device__ __forceinline__ U2 ldg_b128(const void* p) {
    U2 r;
    asm volatile("ld.global.nc.v2.u64 {%0,%1}, [%2];"
                 : "=l"(r.lo), "=l"(r.hi) : "l"(p));
    return r;
}
__device__ __forceinline__ unsigned long long addf32x2(unsigned long long a,
                                                       unsigned long long b) {
    unsigned long long r;
    asm("add.rn.f32x2 %0, %1, %2;" : "=l"(r) : "l"(a), "l"(b));
    return r;
}

// ---------------------------------------------------------------------------
// Inline dtype detection (reference declares int64; JAX w/o x64 emits int32).
// For little-endian int64 indices in [0, 2^31), every odd int32 word is 0.
// For int32 data those words are uniform random gather indices;
// P(first 8 all zero) ~ 1e-42.
// ---------------------------------------------------------------------------
__device__ __forceinline__ bool detect_is64_warp(const void* gidx, int lane) {
    const int* p = (const int*)gidx;
    int w = (lane < 8) ? p[2 * lane + 1] : 0;
    return __all_sync(0xFFFFFFFFu, w == 0);
}

__device__ __forceinline__ int load_idx(const void* p, int i, bool is64) {
    return is64 ? (int)((const long long*)p)[i] : ((const int*)p)[i];
}

// ---------------------------------------------------------------------------
// CSR offsets from sorted segment ids. offsets[s] = first edge with seg >= s.
// One LDG per thread; seg[e-1] via shfl_up (lane 0 loads the extra element).
// ---------------------------------------------------------------------------
__global__ void build_offsets_kernel(const void* __restrict__ seg,
                                     const void* __restrict__ gidx,
                                     int E, int nseg) {
    int e    = blockIdx.x * blockDim.x + threadIdx.x;
    int lane = threadIdx.x & 31;
    bool is64 = detect_is64_warp(gidx, lane);

    int cur = load_idx(seg, e < E ? e : (E - 1), is64);
    int prev = __shfl_up_sync(0xFFFFFFFFu, cur, 1);
    if (lane == 0) prev = (e == 0) ? -1 : load_idx(seg, e - 1, is64);
    if (e >= E) return;

    for (int s = prev + 1; s <= cur; s++) g_offsets[s] = e;
    if (e == E - 1) {
        for (int s = cur + 1; s <= nseg; s++) g_offsets[s] = E;
    }
}

// ---------------------------------------------------------------------------
// Split-warp segmented mean: each HALF-warp (16 lanes) owns one segment; a
// lane owns a float4 slot, so 16 lanes cover the full 256B row. One LDG.128
// per warp fetches two rows (one per half). Prologue/epilogue amortized over
// 2 segments, no cross-half combine needed. Main loop trip count is the
// warp-uniform min(nA, nB); the |nA-nB| remainder is one small divergent
// tail. Block = 4 warps = 8 consecutive segments; the block's contiguous
// index range is staged into smem with one coalesced sweep.
// ---------------------------------------------------------------------------
__global__ void __launch_bounds__(128)
seg_mean_kernel(const float* __restrict__ values,
                const void* __restrict__ gidx,
                float* __restrict__ out, int nseg) {
    __shared__ int s_idx[SMEM_IDX];
    __shared__ int s_off[SPB + 1];

    int tid  = threadIdx.x;
    int lane = tid & 31;
    int w    = tid >> 5;
    int seg0 = blockIdx.x * SPB;
    bool is64 = detect_is64_warp(gidx, lane);

    if (tid <= SPB) {
        int s = seg0 + tid;
        s_off[tid] = g_offsets[s < nseg ? s : nseg];
    }
    __syncthreads();

    int estart = s_off[0];
    int etot   = s_off[SPB] - estart;
    int nsm    = etot < SMEM_IDX ? etot : SMEM_IDX;

    // coalesced stage of all block indices into smem (int64 -> int32 on load)
    for (int i = tid; i < nsm; i += 128)
        s_idx[i] = load_idx(gidx, estart + i, is64);
    __syncthreads();

    int half = lane >> 4;                 // which segment of the pair
    int l16  = lane & 15;                 // float4 slot within row
    int my_seg = seg0 + w * 2 + half;

    // block-local edge range of this half's segment
    int start = s_off[w * 2 + half]     - estart;
    int end   = s_off[w * 2 + half + 1] - estart;
    int n     = end - start;

    // warp-uniform common trip count
    int nOther = __shfl_xor_sync(0xFFFFFFFFu, n, 16);
    int nmin = n < nOther ? n : nOther;

    const char* vb = (const char*)values + l16 * 16;
    bool fast = (etot <= nsm);

    U2 A0; A0.lo = 0ull; A0.hi = 0ull;
    U2 A1; A1.lo = 0ull; A1.hi = 0ull;

    if (fast) {
        int k = 0;
        for (; k + 2 <= nmin; k += 2) {
            int i0 = s_idx[start + k];
            int i1 = s_idx[start + k + 1];
            U2 v0 = ldg_b128(vb + (unsigned)i0 * 256u);
            U2 v1 = ldg_b128(vb + (unsigned)i1 * 256u);
            A0.lo = addf32x2(A0.lo, v0.lo); A0.hi = addf32x2(A0.hi, v0.hi);
            A1.lo = addf32x2(A1.lo, v1.lo); A1.hi = addf32x2(A1.hi, v1.hi);
        }
        if (k < nmin) {
            int i0 = s_idx[start + k];
            U2 v0 = ldg_b128(vb + (unsigned)i0 * 256u);
            A0.lo = addf32x2(A0.lo, v0.lo); A0.hi = addf32x2(A0.hi, v0.hi);
        }
        // divergent tail: only the longer half enters (E[len] ~ 3)
        for (int e = start + nmin; e < end; e++) {
            int i0 = s_idx[e];
            U2 v0 = ldg_b128(vb + (unsigned)i0 * 256u);
            A0.lo = addf32x2(A0.lo, v0.lo); A0.hi = addf32x2(A0.hi, v0.hi);
        }
    } else {
        // overflow fallback (essentially never taken)
        for (int e = start; e < end; e++) {
            int i0 = (e < nsm) ? s_idx[e] : load_idx(gidx, estart + e, is64);
            U2 v0 = ldg_b128(vb + (unsigned)i0 * 256u);
            A0.lo = addf32x2(A0.lo, v0.lo); A0.hi = addf32x2(A0.hi, v0.hi);
        }
    }

    unsigned long long Slo = addf32x2(A0.lo, A1.lo);
    unsigned long long Shi = addf32x2(A0.hi, A1.hi);

    float f0 = __uint_as_float((unsigned)(Slo & 0xFFFFFFFFull));
    float f1 = __uint_as_float((unsigned)(Slo >> 32));
    float f2 = __uint_as_float((unsigned)(Shi & 0xFFFFFFFFull));
    float f3 = __uint_as_float((unsigned)(Shi >> 32));

    float inv = 1.0f / (float)(n > 0 ? n : 1);
    if (my_seg < nseg) {
        float4 r = {f0 * inv, f1 * inv, f2 * inv, f3 * inv};
        ((float4*)(out + (long long)my_seg * 64))[l16] = r;
    }
}

// ---------------------------------------------------------------------------
// launch
// inputs: 0=values [N_SRC,64] f32, 1=gather_idx [E] i64/i32,
//         2=segment_ids [E] i64/i32 (sorted), 3=num_segments (scalar, unused)
// out: [nseg,64] f32, nseg = out_size/64
// ---------------------------------------------------------------------------
extern "C" void kernel_launch(void* const* d_in, const int* in_sizes, int n_in,
                              void* d_out, int out_size) {
    const float* values = (const float*)d_in[0];
    const void*  gidx   = d_in[1];
    const void*  seg    = d_in[2];
    float* out = (float*)d_out;

    int E    = in_sizes[1];
    int nseg = out_size / 64;
    if (nseg > MAX_SEG) nseg = MAX_SEG;

    int bthreads = 256;
    build_offsets_kernel<<<(E + bthreads - 1) / bthreads, bthreads>>>(seg, gidx, E, nseg);

    int blocks = (nseg + SPB - 1) / SPB;
    seg_mean_kernel<<<blocks, 128>>>(values, gidx, out, nseg);
}

// round 13
// speedup vs baseline: 1.1074x; 1.1074x over previous
#include <cuda_runtime.h>
#include <cstdint>

#define MAX_SEG 100001
#define SEGS_PER_BLOCK 4
#define SMEM_IDX 1024   // indices staged per block (4 segments, mean ~51 edges)

// scratch (no cudaMalloc allowed)
__device__ int g_offsets[MAX_SEG + 1];

// ---------------------------------------------------------------------------
// Packed-f32 helpers (sm_103a f32x2 pipe) + raw 128-bit global load.
// ---------------------------------------------------------------------------
struct U2 { unsigned long long lo, hi; };

__device__ __forceinline__ U2 ldg_b128(const void* p) {
    U2 r;
    asm volatile("ld.global.nc.v2.u64 {%0,%1}, [%2];"
                 : "=l"(r.lo), "=l"(r.hi) : "l"(p));
    return r;
}
__device__ __forceinline__ unsigned long long addf32x2(unsigned long long a,
                                                       unsigned long long b) {
    unsigned long long r;
    asm("add.rn.f32x2 %0, %1, %2;" : "=l"(r) : "l"(a), "l"(b));
    return r;
}

// ---------------------------------------------------------------------------
// Inline dtype detection (reference declares int64; JAX w/o x64 emits int32).
// For little-endian int64 indices in [0, 2^31), every odd int32 word is 0.
// For int32 data those words are uniform random gather indices;
// P(first 8 all zero) ~ 1e-42.
// ---------------------------------------------------------------------------
__device__ __forceinline__ bool detect_is64_warp(const void* gidx, int lane) {
    const int* p = (const int*)gidx;
    int w = (lane < 8) ? p[2 * lane + 1] : 0;
    return __all_sync(0xFFFFFFFFu, w == 0);
}

__device__ __forceinline__ int load_idx(const void* p, int i, bool is64) {
    return is64 ? (int)((const long long*)p)[i] : ((const int*)p)[i];
}

// ---------------------------------------------------------------------------
// CSR offsets from sorted segment ids. offsets[s] = first edge with seg >= s.
// Vectorized: each thread owns 4 consecutive edges, loaded with one int4
// (int32) or two longlong2 (int64) -> 5x fewer load instructions. seg[e0-1]
// comes from the neighbor lane's last element via shfl_up; lane 0 loads it.
// ---------------------------------------------------------------------------
__global__ void build_offsets_kernel(const void* __restrict__ seg,
                                     const void* __restrict__ gidx,
                                     int E, int nseg) {
    int t    = blockIdx.x * blockDim.x + threadIdx.x;
    int lane = threadIdx.x & 31;
    bool is64 = detect_is64_warp(gidx, lane);

    int e0 = t * 4;
    int v0, v1, v2, v3;
    if (e0 + 4 <= E) {
        if (is64) {
            const longlong2* p = (const longlong2*)((const long long*)seg + e0);
            longlong2 a = p[0], b = p[1];
            v0 = (int)a.x; v1 = (int)a.y; v2 = (int)b.x; v3 = (int)b.y;
        } else {
            int4 a = *(const int4*)((const int*)seg + e0);
            v0 = a.x; v1 = a.y; v2 = a.z; v3 = a.w;
        }
    } else {
        // tail thread: clamped scalar loads
        int eL = E - 1;
        v0 = load_idx(seg, e0 + 0 < E ? e0 + 0 : eL, is64);
        v1 = load_idx(seg, e0 + 1 < E ? e0 + 1 : eL, is64);
        v2 = load_idx(seg, e0 + 2 < E ? e0 + 2 : eL, is64);
        v3 = load_idx(seg, e0 + 3 < E ? e0 + 3 : eL, is64);
    }

    int prev0 = __shfl_up_sync(0xFFFFFFFFu, v3, 1);
    if (lane == 0) prev0 = (e0 == 0) ? -1 : load_idx(seg, e0 - 1, is64);
    if (e0 >= E) return;

    int cur[4]  = {v0, v1, v2, v3};
    int prv[4]  = {prev0, v0, v1, v2};
    #pragma unroll
    for (int k = 0; k < 4; k++) {
        int e = e0 + k;
        if (e >= E) break;
        for (int s = prv[k] + 1; s <= cur[k]; s++) g_offsets[s] = e;
        if (e == E - 1) {
            for (int s = cur[k] + 1; s <= nseg; s++) g_offsets[s] = E;
        }
    }
}

// ---------------------------------------------------------------------------
// Block = 4 warps = 4 consecutive segments (contiguous edge range, sorted
// ids). Block stages its gather indices into smem with one coalesced sweep.
// Row loop: lane l16=lane&15 owns a float4 slot of the 256B row; half=lane>>4
// selects row e+half of an edge PAIR -> one LDG.128 fetches TWO gathered
// rows (~3.25 warp-instr/edge). Halves combined with 4 shfl_xor(16).
// ---------------------------------------------------------------------------
__global__ void __launch_bounds__(128)
seg_mean_kernel(const float* __restrict__ values,
                const void* __restrict__ gidx,
                float* __restrict__ out, int nseg) {
    __shared__ int s_idx[SMEM_IDX];
    __shared__ int s_off[SEGS_PER_BLOCK + 1];

    int tid  = threadIdx.x;
    int lane = tid & 31;
    int w    = tid >> 5;
    int seg0 = blockIdx.x * SEGS_PER_BLOCK;
    bool is64 = detect_is64_warp(gidx, lane);

    if (tid <= SEGS_PER_BLOCK) {
        int s = seg0 + tid;
        s_off[tid] = g_offsets[s < nseg ? s : nseg];
    }
    __syncthreads();

    int estart = s_off[0];
    int etot   = s_off[SEGS_PER_BLOCK] - estart;
    int nsm    = etot < SMEM_IDX ? etot : SMEM_IDX;

    // coalesced stage of all block indices into smem (int64 -> int32 on load)
    for (int i = tid; i < nsm; i += 128)
        s_idx[i] = load_idx(gidx, estart + i, is64);
    __syncthreads();

    int seg = seg0 + w;
    if (seg >= nseg) return;

    int start = s_off[w]     - estart;   // block-local edge range
    int end   = s_off[w + 1] - estart;
    int n     = end - start;

    int half = lane >> 4;                // which row of the pair
    int l16  = lane & 15;                // float4 slot within row
    const char* vb = (const char*)values + l16 * 16;

    U2 A0; A0.lo = 0ull; A0.hi = 0ull;   // this half's partial (float4)
    U2 A1; A1.lo = 0ull; A1.hi = 0ull;

    int e = start;
    if (end <= nsm) {
        // main: 4 edges (2 pairs) per iteration
        for (; e + 4 <= end; e += 4) {
            int ia = s_idx[e + half];
            int ib = s_idx[e + 2 + half];
            U2 va = ldg_b128(vb + (unsigned)ia * 256u);
            U2 vc = ldg_b128(vb + (unsigned)ib * 256u);
            A0.lo = addf32x2(A0.lo, va.lo); A0.hi = addf32x2(A0.hi, va.hi);
            A1.lo = addf32x2(A1.lo, vc.lo); A1.hi = addf32x2(A1.hi, vc.hi);
        }
        // one remaining pair
        if (e + 2 <= end) {
            int ia = s_idx[e + half];
            U2 va = ldg_b128(vb + (unsigned)ia * 256u);
            A0.lo = addf32x2(A0.lo, va.lo); A0.hi = addf32x2(A0.hi, va.hi);
            e += 2;
        }
        // single remaining edge: only half 0 contributes
        if (e < end) {
            int ia = s_idx[e];
            U2 va = ldg_b128(vb + (unsigned)ia * 256u);
            if (half == 0) {
                A0.lo = addf32x2(A0.lo, va.lo); A0.hi = addf32x2(A0.hi, va.hi);
            }
        }
    } else {
        // overflow fallback (essentially never taken)
        for (; e < end; e++) {
            int ia = (e < nsm) ? s_idx[e] : load_idx(gidx, estart + e, is64);
            U2 va = ldg_b128(vb + (unsigned)ia * 256u);
            if (half == 0) {
                A0.lo = addf32x2(A0.lo, va.lo); A0.hi = addf32x2(A0.hi, va.hi);
            }
        }
    }

    unsigned long long Slo = addf32x2(A0.lo, A1.lo);
    unsigned long long Shi = addf32x2(A0.hi, A1.hi);

    float f0 = __uint_as_float((unsigned)(Slo & 0xFFFFFFFFull));
    float f1 = __uint_as_float((unsigned)(Slo >> 32));
    float f2 = __uint_as_float((unsigned)(Shi & 0xFFFFFFFFull));
    float f3 = __uint_as_float((unsigned)(Shi >> 32));

    // combine the two halves (same l16 slot, xor lane bit 4)
    f0 += __shfl_xor_sync(0xFFFFFFFFu, f0, 16);
    f1 += __shfl_xor_sync(0xFFFFFFFFu, f1, 16);
    f2 += __shfl_xor_sync(0xFFFFFFFFu, f2, 16);
    f3 += __shfl_xor_sync(0xFFFFFFFFu, f3, 16);

    float inv = 1.0f / (float)(n > 0 ? n : 1);
    if (half == 0) {
        float4 r = {f0 * inv, f1 * inv, f2 * inv, f3 * inv};
        ((float4*)(out + (long long)seg * 64))[l16] = r;
    }
}

// ---------------------------------------------------------------------------
// launch
// inputs: 0=values [N_SRC,64] f32, 1=gather_idx [E] i64/i32,
//         2=segment_ids [E] i64/i32 (sorted), 3=num_segments (scalar, unused)
// out: [nseg,64] f32, nseg = out_size/64
// ---------------------------------------------------------------------------
extern "C" void kernel_launch(void* const* d_in, const int* in_sizes, int n_in,
                              void* d_out, int out_size) {
    const float* values = (const float*)d_in[0];
    const void*  gidx   = d_in[1];
    const void*  seg    = d_in[2];
    float* out = (float*)d_out;

    int E    = in_sizes[1];
    int nseg = out_size / 64;
    if (nseg > MAX_SEG) nseg = MAX_SEG;

    int bthreads = 256;
    int bwork = (E + 3) / 4;
    build_offsets_kernel<<<(bwork + bthreads - 1) / bthreads, bthreads>>>(seg, gidx, E, nseg);

    int blocks = (nseg + SEGS_PER_BLOCK - 1) / SEGS_PER_BLOCK;
    seg_mean_kernel<<<blocks, 128>>>(values, gidx, out, nseg);
}

// round 14
// speedup vs baseline: 1.1641x; 1.0512x over previous
#include <cuda_runtime.h>
#include <cstdint>

#define MAX_SEG 100001

// scratch (no cudaMalloc allowed)
__device__ int g_offsets[MAX_SEG + 1];

// ---------------------------------------------------------------------------
// Packed-f32 helpers (sm_103a f32x2 pipe) + raw 128-bit global load.
// ---------------------------------------------------------------------------
struct U2 { unsigned long long lo, hi; };

__device__ __forceinline__ U2 ldg_b128(const void* p) {
    U2 r;
    asm volatile("ld.global.nc.v2.u64 {%0,%1}, [%2];"
                 : "=l"(r.lo), "=l"(r.hi) : "l"(p));
    return r;
}
__device__ __forceinline__ unsigned long long addf32x2(unsigned long long a,
                                                       unsigned long long b) {
    unsigned long long r;
    asm("add.rn.f32x2 %0, %1, %2;" : "=l"(r) : "l"(a), "l"(b));
    return r;
}

// ---------------------------------------------------------------------------
// Inline dtype detection (reference declares int64; JAX w/o x64 emits int32).
// For little-endian int64 indices in [0, 2^31), every odd int32 word is 0.
// For int32 data those words are uniform random gather indices;
// P(first 8 all zero) ~ 1e-42.
// ---------------------------------------------------------------------------
__device__ __forceinline__ bool detect_is64_warp(const void* gidx, int lane) {
    const int* p = (const int*)gidx;
    int w = (lane < 8) ? p[2 * lane + 1] : 0;
    return __all_sync(0xFFFFFFFFu, w == 0);
}

__device__ __forceinline__ int load_idx(const void* p, int i, bool is64) {
    return is64 ? (int)((const long long*)p)[i] : ((const int*)p)[i];
}

// ---------------------------------------------------------------------------
// CSR offsets from sorted segment ids. offsets[s] = first edge with seg >= s.
// Vectorized: each thread owns 4 consecutive edges (one int4 / two
// longlong2); seg[e0-1] via shfl_up of the neighbor's last element.
// ---------------------------------------------------------------------------
__global__ void build_offsets_kernel(const void* __restrict__ seg,
                                     const void* __restrict__ gidx,
                                     int E, int nseg) {
    int t    = blockIdx.x * blockDim.x + threadIdx.x;
    int lane = threadIdx.x & 31;
    bool is64 = detect_is64_warp(gidx, lane);

    int e0 = t * 4;
    int v0, v1, v2, v3;
    if (e0 + 4 <= E) {
        if (is64) {
            const longlong2* p = (const longlong2*)((const long long*)seg + e0);
            longlong2 a = p[0], b = p[1];
            v0 = (int)a.x; v1 = (int)a.y; v2 = (int)b.x; v3 = (int)b.y;
        } else {
            int4 a = *(const int4*)((const int*)seg + e0);
            v0 = a.x; v1 = a.y; v2 = a.z; v3 = a.w;
        }
    } else {
        int eL = E - 1;
        v0 = load_idx(seg, e0 + 0 < E ? e0 + 0 : eL, is64);
        v1 = load_idx(seg, e0 + 1 < E ? e0 + 1 : eL, is64);
        v2 = load_idx(seg, e0 + 2 < E ? e0 + 2 : eL, is64);
        v3 = load_idx(seg, e0 + 3 < E ? e0 + 3 : eL, is64);
    }

    int prev0 = __shfl_up_sync(0xFFFFFFFFu, v3, 1);
    if (lane == 0) prev0 = (e0 == 0) ? -1 : load_idx(seg, e0 - 1, is64);
    if (e0 >= E) return;

    int cur[4] = {v0, v1, v2, v3};
    int prv[4] = {prev0, v0, v1, v2};
    #pragma unroll
    for (int k = 0; k < 4; k++) {
        int e = e0 + k;
        if (e >= E) break;
        for (int s = prv[k] + 1; s <= cur[k]; s++) g_offsets[s] = e;
        if (e == E - 1) {
            for (int s = cur[k] + 1; s <= nseg; s++) g_offsets[s] = E;
        }
    }
}

// ---------------------------------------------------------------------------
// Warp-autonomous segmented mean: one warp per segment, NO smem, NO barriers.
// Lanes 0-1 fetch the segment's two offsets (one sector). Each 32-edge chunk:
// one coalesced index load (gidx[start+lane]), then the pair loop — lane
// l16=lane&15 owns a float4 slot of the 256B row, half=lane>>4 picks row
// e+half of an edge PAIR, so one LDG.128 fetches TWO gathered rows. Indices
// come from register shuffles (no memory dependency). Halves combined with
// 4 shfl_xor(16).
// ---------------------------------------------------------------------------
__global__ void __launch_bounds__(128)
seg_mean_kernel(const float* __restrict__ values,
                const void* __restrict__ gidx,
                float* __restrict__ out, int nseg) {
    int tid  = threadIdx.x;
    int lane = tid & 31;
    int seg  = (blockIdx.x * 128 + tid) >> 5;
    if (seg >= nseg) return;

    bool is64 = detect_is64_warp(gidx, lane);

    // both offsets with one coalesced sector load
    int off = 0;
    if (lane < 2) off = g_offsets[seg + lane];
    int start = __shfl_sync(0xFFFFFFFFu, off, 0);
    int end   = __shfl_sync(0xFFFFFFFFu, off, 1);
    int n     = end - start;

    int half = lane >> 4;                // which row of the pair
    int l16  = lane & 15;                // float4 slot within row
    const char* vb = (const char*)values + l16 * 16;

    U2 A0; A0.lo = 0ull; A0.hi = 0ull;
    U2 A1; A1.lo = 0ull; A1.hi = 0ull;

    for (int base = 0; base < n; base += 32) {
        int m = n - base;
        if (m > 32) m = 32;
        // one coalesced load of up to 32 indices for this chunk
        int myidx = 0;
        if (lane < m) myidx = load_idx(gidx, start + base + lane, is64);

        int j = 0;
        // main: 4 edges (2 pairs) per iteration
        for (; j + 4 <= m; j += 4) {
            int ia = __shfl_sync(0xFFFFFFFFu, myidx, j + half);
            int ib = __shfl_sync(0xFFFFFFFFu, myidx, j + 2 + half);
            U2 va = ldg_b128(vb + (unsigned)ia * 256u);
            U2 vc = ldg_b128(vb + (unsigned)ib * 256u);
            A0.lo = addf32x2(A0.lo, va.lo); A0.hi = addf32x2(A0.hi, va.hi);
            A1.lo = addf32x2(A1.lo, vc.lo); A1.hi = addf32x2(A1.hi, vc.hi);
        }
        // one remaining pair
        if (j + 2 <= m) {
            int ia = __shfl_sync(0xFFFFFFFFu, myidx, j + half);
            U2 va = ldg_b128(vb + (unsigned)ia * 256u);
            A0.lo = addf32x2(A0.lo, va.lo); A0.hi = addf32x2(A0.hi, va.hi);
            j += 2;
        }
        // single remaining edge: only half 0 contributes
        if (j < m) {
            int ia = __shfl_sync(0xFFFFFFFFu, myidx, j);
            U2 va = ldg_b128(vb + (unsigned)ia * 256u);
            if (half == 0) {
                A0.lo = addf32x2(A0.lo, va.lo); A0.hi = addf32x2(A0.hi, va.hi);
            }
        }
    }

    unsigned long long Slo = addf32x2(A0.lo, A1.lo);
    unsigned long long Shi = addf32x2(A0.hi, A1.hi);

    float f0 = __uint_as_float((unsigned)(Slo & 0xFFFFFFFFull));
    float f1 = __uint_as_float((unsigned)(Slo >> 32));
    float f2 = __uint_as_float((unsigned)(Shi & 0xFFFFFFFFull));
    float f3 = __uint_as_float((unsigned)(Shi >> 32));

    // combine the two halves (same l16 slot, xor lane bit 4)
    f0 += __shfl_xor_sync(0xFFFFFFFFu, f0, 16);
    f1 += __shfl_xor_sync(0xFFFFFFFFu, f1, 16);
    f2 += __shfl_xor_sync(0xFFFFFFFFu, f2, 16);
    f3 += __shfl_xor_sync(0xFFFFFFFFu, f3, 16);

    float inv = 1.0f / (float)(n > 0 ? n : 1);
    if (half == 0) {
        float4 r = {f0 * inv, f1 * inv, f2 * inv, f3 * inv};
        ((float4*)(out + (long long)seg * 64))[l16] = r;
    }
}

// ---------------------------------------------------------------------------
// launch
// inputs: 0=values [N_SRC,64] f32, 1=gather_idx [E] i64/i32,
//         2=segment_ids [E] i64/i32 (sorted), 3=num_segments (scalar, unused)
// out: [nseg,64] f32, nseg = out_size/64
// ---------------------------------------------------------------------------
extern "C" void kernel_launch(void* const* d_in, const int* in_sizes, int n_in,
                              void* d_out, int out_size) {
    const float* values = (const float*)d_in[0];
    const void*  gidx   = d_in[1];
    const void*  seg    = d_in[2];
    float* out = (float*)d_out;

    int E    = in_sizes[1];
    int nseg = out_size / 64;
    if (nseg > MAX_SEG) nseg = MAX_SEG;

    int bthreads = 256;
    int bwork = (E + 3) / 4;
    build_offsets_kernel<<<(bwork + bthreads - 1) / bthreads, bthreads>>>(seg, gidx, E, nseg);

    int warps_per_block = 4;
    int blocks = (nseg + warps_per_block - 1) / warps_per_block;
    seg_mean_kernel<<<blocks, 128>>>(values, gidx, out, nseg);
}

// round 15
// speedup vs baseline: 1.1775x; 1.0115x over previous
#include <cuda_runtime.h>
#include <cstdint>

#define MAX_SEG 100001

// scratch (no cudaMalloc allowed)
__device__ int g_offsets[MAX_SEG + 1];

// ---------------------------------------------------------------------------
// Packed-f32 helpers (sm_103a f32x2 pipe) + raw 128-bit global load.
// ---------------------------------------------------------------------------
struct U2 { unsigned long long lo, hi; };

__device__ __forceinline__ U2 ldg_b128(const void* p) {
    U2 r;
    asm volatile("ld.global.nc.v2.u64 {%0,%1}, [%2];"
                 : "=l"(r.lo), "=l"(r.hi) : "l"(p));
    return r;
}
__device__ __forceinline__ unsigned long long addf32x2(unsigned long long a,
                                                       unsigned long long b) {
    unsigned long long r;
    asm("add.rn.f32x2 %0, %1, %2;" : "=l"(r) : "l"(a), "l"(b));
    return r;
}

// ---------------------------------------------------------------------------
// Inline dtype detection (reference declares int64; JAX w/o x64 emits int32).
// For little-endian int64 indices in [0, 2^31), every odd int32 word is 0.
// For int32 data those words are uniform random gather indices;
// P(first 8 all zero) ~ 1e-42.
// ---------------------------------------------------------------------------
__device__ __forceinline__ bool detect_is64_warp(const void* gidx, int lane) {
    const int* p = (const int*)gidx;
    int w = (lane < 8) ? p[2 * lane + 1] : 0;
    return __all_sync(0xFFFFFFFFu, w == 0);
}

__device__ __forceinline__ int load_idx(const void* p, int i, bool is64) {
    return is64 ? (int)((const long long*)p)[i] : ((const int*)p)[i];
}

// ---------------------------------------------------------------------------
// CSR offsets from sorted segment ids. offsets[s] = first edge with seg >= s.
// Each thread owns 8 consecutive edges (2x int4 / 4x longlong2 loads);
// seg[e0-1] comes from the neighbor lane's last element via shfl_up.
// ---------------------------------------------------------------------------
__global__ void __launch_bounds__(256)
build_offsets_kernel(const void* __restrict__ seg,
                     const void* __restrict__ gidx,
                     int E, int nseg) {
    int t    = blockIdx.x * blockDim.x + threadIdx.x;
    int lane = threadIdx.x & 31;
    bool is64 = detect_is64_warp(gidx, lane);

    int e0 = t * 8;
    int v[8];
    if (e0 + 8 <= E) {
        if (is64) {
            const longlong2* p = (const longlong2*)((const long long*)seg + e0);
            longlong2 a = p[0], b = p[1], c = p[2], d = p[3];
            v[0] = (int)a.x; v[1] = (int)a.y; v[2] = (int)b.x; v[3] = (int)b.y;
            v[4] = (int)c.x; v[5] = (int)c.y; v[6] = (int)d.x; v[7] = (int)d.y;
        } else {
            const int4* p = (const int4*)((const int*)seg + e0);
            int4 a = p[0], b = p[1];
            v[0] = a.x; v[1] = a.y; v[2] = a.z; v[3] = a.w;
            v[4] = b.x; v[5] = b.y; v[6] = b.z; v[7] = b.w;
        }
    } else {
        int eL = E - 1;
        #pragma unroll
        for (int k = 0; k < 8; k++)
            v[k] = load_idx(seg, e0 + k < E ? e0 + k : eL, is64);
    }

    int prev0 = __shfl_up_sync(0xFFFFFFFFu, v[7], 1);
    if (lane == 0) prev0 = (e0 == 0) ? -1 : load_idx(seg, e0 - 1, is64);
    if (e0 >= E) return;

    int prev = prev0;
    #pragma unroll
    for (int k = 0; k < 8; k++) {
        int e = e0 + k;
        if (e >= E) break;
        for (int s = prev + 1; s <= v[k]; s++) g_offsets[s] = e;
        if (e == E - 1) {
            for (int s = v[k] + 1; s <= nseg; s++) g_offsets[s] = E;
        }
        prev = v[k];
    }
}

// ---------------------------------------------------------------------------
// Warp-autonomous segmented mean: one warp per segment, NO smem, NO barriers.
// Lanes 0-1 fetch the segment's two offsets (one sector). Each 32-edge chunk:
// one coalesced index load (gidx[start+lane]), then the pair loop — lane
// l16=lane&15 owns a float4 slot of the 256B row, half=lane>>4 picks row
// e+half of an edge PAIR, so one LDG.128 fetches TWO gathered rows. Indices
// come from register shuffles (no memory dependency). Halves combined with
// 4 shfl_xor(16).
// ---------------------------------------------------------------------------
__global__ void __launch_bounds__(128)
seg_mean_kernel(const float* __restrict__ values,
                const void* __restrict__ gidx,
                float* __restrict__ out, int nseg) {
    int tid  = threadIdx.x;
    int lane = tid & 31;
    int seg  = (blockIdx.x * 128 + tid) >> 5;
    if (seg >= nseg) return;

    bool is64 = detect_is64_warp(gidx, lane);

    // both offsets with one coalesced sector load
    int off = 0;
    if (lane < 2) off = g_offsets[seg + lane];
    int start = __shfl_sync(0xFFFFFFFFu, off, 0);
    int end   = __shfl_sync(0xFFFFFFFFu, off, 1);
    int n     = end - start;

    int half = lane >> 4;                // which row of the pair
    int l16  = lane & 15;                // float4 slot within row
    const char* vb = (const char*)values + l16 * 16;

    U2 A0; A0.lo = 0ull; A0.hi = 0ull;
    U2 A1; A1.lo = 0ull; A1.hi = 0ull;

    for (int base = 0; base < n; base += 32) {
        int m = n - base;
        if (m > 32) m = 32;
        // one coalesced load of up to 32 indices for this chunk
        int myidx = 0;
        if (lane < m) myidx = load_idx(gidx, start + base + lane, is64);

        int j = 0;
        // main: 4 edges (2 pairs) per iteration
        for (; j + 4 <= m; j += 4) {
            int ia = __shfl_sync(0xFFFFFFFFu, myidx, j + half);
            int ib = __shfl_sync(0xFFFFFFFFu, myidx, j + 2 + half);
            U2 va = ldg_b128(vb + (unsigned)ia * 256u);
            U2 vc = ldg_b128(vb + (unsigned)ib * 256u);
            A0.lo = addf32x2(A0.lo, va.lo); A0.hi = addf32x2(A0.hi, va.hi);
            A1.lo = addf32x2(A1.lo, vc.lo); A1.hi = addf32x2(A1.hi, vc.hi);
        }
        // one remaining pair
        if (j + 2 <= m) {
            int ia = __shfl_sync(0xFFFFFFFFu, myidx, j + half);
            U2 va = ldg_b128(vb + (unsigned)ia * 256u);
            A0.lo = addf32x2(A0.lo, va.lo); A0.hi = addf32x2(A0.hi, va.hi);
            j += 2;
        }
        // single remaining edge: only half 0 contributes
        if (j < m) {
            int ia = __shfl_sync(0xFFFFFFFFu, myidx, j);
            U2 va = ldg_b128(vb + (unsigned)ia * 256u);
            if (half == 0) {
                A0.lo = addf32x2(A0.lo, va.lo); A0.hi = addf32x2(A0.hi, va.hi);
            }
        }
    }

    unsigned long long Slo = addf32x2(A0.lo, A1.lo);
    unsigned long long Shi = addf32x2(A0.hi, A1.hi);

    float f0 = __uint_as_float((unsigned)(Slo & 0xFFFFFFFFull));
    float f1 = __uint_as_float((unsigned)(Slo >> 32));
    float f2 = __uint_as_float((unsigned)(Shi & 0xFFFFFFFFull));
    float f3 = __uint_as_float((unsigned)(Shi >> 32));

    // combine the two halves (same l16 slot, xor lane bit 4)
    f0 += __shfl_xor_sync(0xFFFFFFFFu, f0, 16);
    f1 += __shfl_xor_sync(0xFFFFFFFFu, f1, 16);
    f2 += __shfl_xor_sync(0xFFFFFFFFu, f2, 16);
    f3 += __shfl_xor_sync(0xFFFFFFFFu, f3, 16);

    float inv = 1.0f / (float)(n > 0 ? n : 1);
    if (half == 0) {
        float4 r = {f0 * inv, f1 * inv, f2 * inv, f3 * inv};
        ((float4*)(out + (long long)seg * 64))[l16] = r;
    }
}

// ---------------------------------------------------------------------------
// launch
// inputs: 0=values [N_SRC,64] f32, 1=gather_idx [E] i64/i32,
//         2=segment_ids [E] i64/i32 (sorted), 3=num_segments (scalar, unused)
// out: [nseg,64] f32, nseg = out_size/64
// ---------------------------------------------------------------------------
extern "C" void kernel_launch(void* const* d_in, const int* in_sizes, int n_in,
                              void* d_out, int out_size) {
    const float* values = (const float*)d_in[0];
    const void*  gidx   = d_in[1];
    const void*  seg    = d_in[2];
    float* out = (float*)d_out;

    int E    = in_sizes[1];
    int nseg = out_size / 64;
    if (nseg > MAX_SEG) nseg = MAX_SEG;

    int bthreads = 256;
    int bwork = (E + 7) / 8;
    build_offsets_kernel<<<(bwork + bthreads - 1) / bthreads, bthreads>>>(seg, gidx, E, nseg);

    int warps_per_block = 4;
    int blocks = (nseg + warps_per_block - 1) / warps_per_block;
    seg_mean_kernel<<<blocks, 128>>>(values, gidx, out, nseg);
}